// round 1
// baseline (speedup 1.0000x reference)
#include <cuda_runtime.h>
#include <cstdint>

// Problem dims
#define B_   32
#define T_   4096
#define DIN_ 256
#define H_   256
#define BT_  (B_ * T_)

// Scan chunking
#define LCH 128
#define NCH (T_ / LCH)   // 32

// ---------------- scratch (device globals; no allocation) ----------------
__device__ float g_k [(size_t)BT_ * H_];   // z-gate pre-activation
__device__ float g_kh[(size_t)BT_ * H_];   // h-tilde pre-activation
__device__ float g_aggP[B_ * NCH * H_];
__device__ float g_aggS[B_ * NCH * H_];
__device__ float g_incH[B_ * NCH * H_];
__device__ int   g_flag[B_ * NCH];

__global__ void init_flags_kernel() {
    int i = blockIdx.x * blockDim.x + threadIdx.x;
    if (i < B_ * NCH) g_flag[i] = 0;
}

// ---------------- GEMM: out[m][n] = sum_k X[m][k] * W[n][k] + bias[n] -----
// tf32 mma.sync m16n8k8, tile M=128 x N=64, K-chunk=32, 256 threads (8 warps, 4x2)

#define TM 128
#define TN 64
#define TK 32
#define LDS_PAD 4
#define LDSW (TK + LDS_PAD)   // 36 floats row stride (144B, 16B aligned)

__device__ __forceinline__ float f2tf32(float x) {
    uint32_t u;
    asm("cvt.rna.tf32.f32 %0, %1;" : "=r"(u) : "f"(x));
    return __uint_as_float(u);
}

__global__ void __launch_bounds__(256, 2) gemm_kernel(
    const float* __restrict__ X,
    const float* __restrict__ Wz, const float* __restrict__ bz,
    const float* __restrict__ Wh, const float* __restrict__ bh)
{
    const float* W    = blockIdx.z ? Wh : Wz;
    const float* bias = blockIdx.z ? bh : bz;
    float* dst        = blockIdx.z ? g_kh : g_k;

    __shared__ float sA[TM][LDSW];
    __shared__ float sB[TN][LDSW];

    const int tid  = threadIdx.x;
    const int lane = tid & 31;
    const int wid  = tid >> 5;
    const int wm   = wid >> 1;   // 0..3  (M direction, 32 rows each)
    const int wn   = wid & 1;    // 0..1  (N direction, 32 cols each)
    const int grp  = lane >> 2;  // 0..7
    const int tg   = lane & 3;   // 0..3

    const size_t m0 = (size_t)blockIdx.x * TM;
    const int    n0 = blockIdx.y * TN;

    float acc[2][4][4];
    #pragma unroll
    for (int a = 0; a < 2; a++)
        #pragma unroll
        for (int b = 0; b < 4; b++)
            #pragma unroll
            for (int c = 0; c < 4; c++) acc[a][b][c] = 0.f;

    const float4* X4 = reinterpret_cast<const float4*>(X);
    const float4* W4 = reinterpret_cast<const float4*>(W);

    float4 bufA[4], bufB[2];

    auto ldg = [&](int kc) {
        #pragma unroll
        for (int i = 0; i < 4; i++) {
            int q = tid + i * 256;
            int r = q >> 3, c4 = q & 7;
            bufA[i] = X4[(m0 + r) * (DIN_ / 4) + kc * (TK / 4) + c4];
        }
        #pragma unroll
        for (int i = 0; i < 2; i++) {
            int q = tid + i * 256;
            int r = q >> 3, c4 = q & 7;
            bufB[i] = W4[(size_t)(n0 + r) * (DIN_ / 4) + kc * (TK / 4) + c4];
        }
    };
    auto sts = [&]() {
        #pragma unroll
        for (int i = 0; i < 4; i++) {
            int q = tid + i * 256;
            int r = q >> 3, c4 = q & 7;
            float4 v = bufA[i];
            v.x = f2tf32(v.x); v.y = f2tf32(v.y); v.z = f2tf32(v.z); v.w = f2tf32(v.w);
            *reinterpret_cast<float4*>(&sA[r][c4 * 4]) = v;
        }
        #pragma unroll
        for (int i = 0; i < 2; i++) {
            int q = tid + i * 256;
            int r = q >> 3, c4 = q & 7;
            float4 v = bufB[i];
            v.x = f2tf32(v.x); v.y = f2tf32(v.y); v.z = f2tf32(v.z); v.w = f2tf32(v.w);
            *reinterpret_cast<float4*>(&sB[r][c4 * 4]) = v;
        }
    };

    ldg(0);
    sts();
    __syncthreads();

    #pragma unroll 1
    for (int kc = 0; kc < DIN_ / TK; kc++) {
        if (kc + 1 < DIN_ / TK) ldg(kc + 1);

        #pragma unroll
        for (int ks = 0; ks < TK / 8; ks++) {
            uint32_t afr[2][4];
            uint32_t bfr[4][2];
            #pragma unroll
            for (int mt = 0; mt < 2; mt++) {
                int r0 = wm * 32 + mt * 16 + grp;
                afr[mt][0] = __float_as_uint(sA[r0    ][ks * 8 + tg    ]);
                afr[mt][1] = __float_as_uint(sA[r0 + 8][ks * 8 + tg    ]);
                afr[mt][2] = __float_as_uint(sA[r0    ][ks * 8 + tg + 4]);
                afr[mt][3] = __float_as_uint(sA[r0 + 8][ks * 8 + tg + 4]);
            }
            #pragma unroll
            for (int nt = 0; nt < 4; nt++) {
                int nr = wn * 32 + nt * 8 + grp;
                bfr[nt][0] = __float_as_uint(sB[nr][ks * 8 + tg    ]);
                bfr[nt][1] = __float_as_uint(sB[nr][ks * 8 + tg + 4]);
            }
            #pragma unroll
            for (int mt = 0; mt < 2; mt++)
                #pragma unroll
                for (int nt = 0; nt < 4; nt++) {
                    asm volatile(
                        "mma.sync.aligned.m16n8k8.row.col.f32.tf32.tf32.f32 "
                        "{%0,%1,%2,%3}, {%4,%5,%6,%7}, {%8,%9}, {%0,%1,%2,%3};\n"
                        : "+f"(acc[mt][nt][0]), "+f"(acc[mt][nt][1]),
                          "+f"(acc[mt][nt][2]), "+f"(acc[mt][nt][3])
                        : "r"(afr[mt][0]), "r"(afr[mt][1]),
                          "r"(afr[mt][2]), "r"(afr[mt][3]),
                          "r"(bfr[nt][0]), "r"(bfr[nt][1]));
                }
        }
        __syncthreads();
        if (kc + 1 < DIN_ / TK) {
            sts();
            __syncthreads();
        }
    }

    // epilogue
    #pragma unroll
    for (int mt = 0; mt < 2; mt++) {
        #pragma unroll
        for (int nt = 0; nt < 4; nt++) {
            int col = n0 + wn * 32 + nt * 8 + 2 * tg;
            float bv0 = bias[col], bv1 = bias[col + 1];
            size_t r0 = m0 + wm * 32 + mt * 16 + grp;
            float2 v0 = make_float2(acc[mt][nt][0] + bv0, acc[mt][nt][1] + bv1);
            float2 v1 = make_float2(acc[mt][nt][2] + bv0, acc[mt][nt][3] + bv1);
            *reinterpret_cast<float2*>(&dst[r0 * H_ + col])       = v0;
            *reinterpret_cast<float2*>(&dst[(r0 + 8) * H_ + col]) = v1;
        }
    }
}

// ---------------- scan: h_t = c_t h_{t-1} + v_t,  chunked + lookback -------

__device__ __forceinline__ float sigmoid_f(float x) {
    return __fdividef(1.f, 1.f + __expf(-x));
}
__device__ __forceinline__ float g_act(float x) {
    return x >= 0.f ? x + 0.5f : sigmoid_f(x);
}

__global__ void __launch_bounds__(256) scan_kernel(
    const float* __restrict__ h0, float* __restrict__ out)
{
    const int c = blockIdx.x;   // chunk
    const int b = blockIdx.y;   // batch
    const int h = threadIdx.x;  // channel

    const size_t base = ((size_t)b * T_ + (size_t)c * LCH) * H_ + h;

    // ---- pass 1: chunk aggregate (P = prod c_t, S = scan with 0 init) ----
    float P = 1.f, S = 0.f;
    #pragma unroll 4
    for (int t = 0; t < LCH; t++) {
        float k  = g_k [base + (size_t)t * H_];
        float kh = g_kh[base + (size_t)t * H_];
        float z  = sigmoid_f(k);
        float cc = 1.f - z;
        float vv = z * g_act(kh);
        S = fmaf(cc, S, vv);
        P *= cc;
    }

    const int aidx = (b * NCH + c) * H_ + h;
    __shared__ int sflag;
    float h_in;

    if (c == 0) {
        h_in = g_act(h0[b * H_ + h]);
    } else {
        // publish aggregate
        g_aggP[aidx] = P;
        g_aggS[aidx] = S;
        __threadfence();
        __syncthreads();
        if (h == 0) atomicExch(&g_flag[b * NCH + c], 1);

        // decoupled lookback
        float accP = 1.f, accS = 0.f;
        int j = c - 1;
        while (true) {
            if (h == 0) {
                int f;
                do { f = *(volatile int*)(g_flag + b * NCH + j); } while (f == 0);
                sflag = f;
            }
            __syncthreads();
            int f = sflag;
            __threadfence();  // acquire: order data loads after flag observation
            int jidx = (b * NCH + j) * H_ + h;
            if (f == 2) {
                float Hj = g_incH[jidx];
                h_in = fmaf(accP, Hj, accS);
                break;
            } else {
                float Pj = g_aggP[jidx];
                float Sj = g_aggS[jidx];
                accS = fmaf(accP, Sj, accS);
                accP *= Pj;
                j--;
            }
            __syncthreads();  // before sflag reuse
        }
    }

    // publish inclusive prefix
    float Hc = fmaf(P, h_in, S);
    g_incH[aidx] = Hc;
    __threadfence();
    __syncthreads();
    if (h == 0) atomicExch(&g_flag[b * NCH + c], 2);

    // ---- pass 2: recompute c,v (L2-hot) and emit outputs ----
    float hv = h_in;
    #pragma unroll 4
    for (int t = 0; t < LCH; t++) {
        float k  = g_k [base + (size_t)t * H_];
        float kh = g_kh[base + (size_t)t * H_];
        float z  = sigmoid_f(k);
        float cc = 1.f - z;
        float vv = z * g_act(kh);
        hv = fmaf(cc, hv, vv);
        out[base + (size_t)t * H_] = hv;
    }
}

// ---------------- launch -------------------------------------------------
extern "C" void kernel_launch(void* const* d_in, const int* in_sizes, int n_in,
                              void* d_out, int out_size)
{
    const float* x  = (const float*)d_in[0];
    const float* h0 = (const float*)d_in[1];
    const float* Wz = (const float*)d_in[2];
    const float* bz = (const float*)d_in[3];
    const float* Wh = (const float*)d_in[4];
    const float* bh = (const float*)d_in[5];
    float* out = (float*)d_out;

    init_flags_kernel<<<1, 1024>>>();

    dim3 ggrid(BT_ / TM, H_ / TN, 2);   // 1024 x 4 x 2
    gemm_kernel<<<ggrid, 256>>>(x, Wz, bz, Wh, bh);

    dim3 sgrid(NCH, B_);                // 32 x 32
    scan_kernel<<<sgrid, 256>>>(h0, out);
}